// round 10
// baseline (speedup 1.0000x reference)
#include <cuda_runtime.h>

#define BATCH 8
#define H 1024
#define W 1024
#define HW (H*W)

// Pass-1: NO shared memory, NO barrier. Block (64,4)=256 thr.
// Each thread: 4 consecutive output rows x 4 cols, loading 6 gray rows directly.
// Grid: (1024/256, 1024/16, 8) = (4, 64, 8); r0 = by*16 + ty*4.
#define P1BX 4
#define P1BY 64
#define PBLK (P1BX * P1BY)   // 256 partials per batch

__device__ float2 g_part[BATCH * PBLK];   // rewritten fully every launch
__device__ float2 g_norm[BATCH];          // rewritten fully every launch

__device__ __forceinline__ float gray3(float r, float g, float b) {
    return 0.3f * r + 0.59f * g + 0.11f * b;
}

// One stencil output: rows (t, m, b) each {L, v4, R}, output column k (0..3).
__device__ __forceinline__ float stencil1(
    float tL, float4 t4, float tR,
    float mL, float4 m4, float mR,
    float bL, float4 b4, float bR,
    int k)
{
    float t[6]  = {tL, t4.x, t4.y, t4.z, t4.w, tR};
    float m[6]  = {mL, m4.x, m4.y, m4.z, m4.w, mR};
    float bo[6] = {bL, b4.x, b4.y, b4.z, b4.w, bR};
    float g   = m[k + 1];
    float acc = 128.0f * t[k]  + 64.0f * t[k + 1] + 32.0f * t[k + 2]
              +   1.0f * m[k]  + 16.0f * m[k + 2]
              +   2.0f * bo[k] +  4.0f * bo[k + 1] + 8.0f * bo[k + 2];
    return 0.5f * (g + 1.0f) - (0.5f / 255.0f) * acc;
}

__global__ __launch_bounds__(256)
void ltpe_pass1(const float* __restrict__ x, float* __restrict__ out) {
    __shared__ float2 wred[8];

    const int b    = blockIdx.z;
    const int gx   = blockIdx.x * 256 + 4 * threadIdx.x;   // 4 cols per thread
    const int r0   = blockIdx.y * 16 + threadIdx.y * 4;    // 4 rows per thread
    const int tid  = threadIdx.y * 64 + threadIdx.x;
    const int lane = tid & 31;
    const unsigned FULL = 0xFFFFFFFFu;

    const float* __restrict__ xr = x + (size_t)b * 3 * HW;
    const float* __restrict__ xg = xr + HW;
    const float* __restrict__ xb = xg + HW;

    // ---- Load 6 gray rows (r0-1 .. r0+4): clamped addresses, zero-select.
    // 18 independent LDG.128 in flight; no smem, no barrier.
    float4 q[6];
    #pragma unroll
    for (int j = 0; j < 6; j++) {
        const int gy  = r0 - 1 + j;
        const int gyc = gy < 0 ? 0 : (gy > H - 1 ? H - 1 : gy);
        const int o   = gyc * W + gx;
        float4 r4 = __ldcs((const float4*)(xr + o));
        float4 g4 = __ldcs((const float4*)(xg + o));
        float4 b4 = __ldcs((const float4*)(xb + o));
        const bool v = (gy >= 0) && (gy < H);
        q[j] = v ? make_float4(gray3(r4.x, g4.x, b4.x), gray3(r4.y, g4.y, b4.y),
                               gray3(r4.z, g4.z, b4.z), gray3(r4.w, g4.w, b4.w))
                 : make_float4(0.f, 0.f, 0.f, 0.f);
    }

    // ---- Horizontal neighbors via shuffle; lanes 0/31 patch from global ----
    float L[6], R[6];
    #pragma unroll
    for (int j = 0; j < 6; j++) {
        L[j] = __shfl_up_sync  (FULL, q[j].w, 1);
        R[j] = __shfl_down_sync(FULL, q[j].x, 1);
    }
    if (lane == 0) {
        const int gxl = gx - 1;                // warp-left column
        #pragma unroll
        for (int j = 0; j < 6; j++) {
            const int gy  = r0 - 1 + j;
            const int gyc = gy < 0 ? 0 : (gy > H - 1 ? H - 1 : gy);
            float v = 0.0f;
            if (gxl >= 0 && gy >= 0 && gy < H) {
                const int o = gyc * W + gxl;
                v = gray3(__ldcs(xr + o), __ldcs(xg + o), __ldcs(xb + o));
            }
            L[j] = v;
        }
    }
    if (lane == 31) {
        const int gxr = gx + 4;                // warp-right column
        #pragma unroll
        for (int j = 0; j < 6; j++) {
            const int gy  = r0 - 1 + j;
            const int gyc = gy < 0 ? 0 : (gy > H - 1 ? H - 1 : gy);
            float v = 0.0f;
            if (gxr < W && gy >= 0 && gy < H) {
                const int o = gyc * W + gxr;
                v = gray3(__ldcs(xr + o), __ldcs(xg + o), __ldcs(xb + o));
            }
            R[j] = v;
        }
    }

    // ---- Stencil rows r0 .. r0+3, store scratch, accumulate sums ----
    float s = 0.0f, s2 = 0.0f;
    float* __restrict__ obase = out + (size_t)b * 3 * HW;

    #pragma unroll
    for (int i = 0; i < 4; i++) {
        float4 ov;
        float* op = (float*)&ov;
        #pragma unroll
        for (int k = 0; k < 4; k++) {
            float o = stencil1(L[i],     q[i],     R[i],
                               L[i + 1], q[i + 1], R[i + 1],
                               L[i + 2], q[i + 2], R[i + 2], k);
            op[k] = o;
            s  += o;
            s2 += o * o;
        }
        // scratch write: default policy -> stays in L2 for pass 2
        *(float4*)(obase + (r0 + i) * W + gx) = ov;
    }

    // ---- Block reduction -> one float2 partial per block ----
    #pragma unroll
    for (int off = 16; off > 0; off >>= 1) {
        s  += __shfl_down_sync(FULL, s,  off);
        s2 += __shfl_down_sync(FULL, s2, off);
    }
    if (lane == 0) wred[tid >> 5] = make_float2(s, s2);
    __syncthreads();
    if (tid == 0) {
        float ts = 0.0f, ts2 = 0.0f;
        #pragma unroll
        for (int w = 0; w < 8; w++) { ts += wred[w].x; ts2 += wred[w].y; }
        g_part[b * PBLK + blockIdx.y * P1BX + blockIdx.x] = make_float2(ts, ts2);
    }
}

// Tiny per-batch reduction: 8 blocks x 256 threads over 256 partials each.
__global__ __launch_bounds__(256)
void ltpe_norm(void) {
    __shared__ double rs[8], rs2[8];
    const int b   = blockIdx.x;
    const int tid = threadIdx.x;

    float2 p = g_part[b * PBLK + tid];
    double s  = (double)p.x;
    double s2 = (double)p.y;
    #pragma unroll
    for (int off = 16; off > 0; off >>= 1) {
        s  += __shfl_down_sync(0xFFFFFFFFu, s,  off);
        s2 += __shfl_down_sync(0xFFFFFFFFu, s2, off);
    }
    if ((tid & 31) == 0) { rs[tid >> 5] = s; rs2[tid >> 5] = s2; }
    __syncthreads();
    if (tid == 0) {
        double ts = 0.0, ts2 = 0.0;
        #pragma unroll
        for (int w = 0; w < 8; w++) { ts += rs[w]; ts2 += rs2[w]; }
        double mean = ts * (1.0 / HW);
        double var  = ts2 * (1.0 / HW) - mean * mean;
        g_norm[b] = make_float2((float)mean, rsqrtf((float)var + 1e-5f));
    }
}

// Pass 2: each thread handles 4 independent float4 chunks (MLP=4).
__global__ __launch_bounds__(256)
void ltpe_pass2(float* __restrict__ out) {
    const int b   = blockIdx.y;
    const int tid = threadIdx.x;

    const float2 nm  = g_norm[b];
    const float m    = nm.x;
    const float rstd = nm.y;

    float* __restrict__ base = out + (size_t)b * 3 * HW;
    const int i0 = blockIdx.x * (256 * 4 * 4);   // floats

    float4 v[4];
    #pragma unroll
    for (int k = 0; k < 4; k++)
        v[k] = __ldcs((const float4*)(base + i0 + (k * 256 + tid) * 4));

    #pragma unroll
    for (int k = 0; k < 4; k++) {
        v[k].x = (v[k].x - m) * rstd;
        v[k].y = (v[k].y - m) * rstd;
        v[k].z = (v[k].z - m) * rstd;
        v[k].w = (v[k].w - m) * rstd;
    }

    #pragma unroll
    for (int k = 0; k < 4; k++) {
        const int i = i0 + (k * 256 + tid) * 4;
        __stcs((float4*)(base + i),          v[k]);
        __stcs((float4*)(base + HW + i),     v[k]);
        __stcs((float4*)(base + 2 * HW + i), v[k]);
    }
}

extern "C" void kernel_launch(void* const* d_in, const int* in_sizes, int n_in,
                              void* d_out, int out_size) {
    const float* x = (const float*)d_in[0];
    float* out = (float*)d_out;

    dim3 blk1(64, 4);
    dim3 grd1(P1BX, P1BY, BATCH);
    ltpe_pass1<<<grd1, blk1>>>(x, out);

    ltpe_norm<<<BATCH, 256>>>();

    dim3 grd2(HW / 4 / 256 / 4, BATCH);   // 256 x 8
    ltpe_pass2<<<grd2, 256>>>(out);
}

// round 11
// speedup vs baseline: 1.1498x; 1.1498x over previous
#include <cuda_runtime.h>

#define BATCH 8
#define H 1024
#define W 1024
#define HW (H*W)

// Pass-1 tiling: 256 wide x 8 tall, 256 threads = (64,4), 2 CONSECUTIVE rows/thread
#define TW 256
#define TH 8
#define SH (TH + 2)          // 10 smem rows
#define SSTRIDE 264          // floats per smem row; interior cols [4,260), halo scalars at 3 / 260
#define BLKX (W / TW)        // 4
#define BLKY (H / TH)        // 128
#define PBLK (BLKX * BLKY)   // 512 partials per batch

__device__ float2 g_part[BATCH * PBLK];   // rewritten fully every launch
__device__ float2 g_norm[BATCH];          // rewritten fully every launch

__device__ __forceinline__ float gray3(float r, float g, float b) {
    return 0.3f * r + 0.59f * g + 0.11f * b;
}

// One stencil output: rows (t, m, b) each given as {L, v4, R}, output column k (0..3).
__device__ __forceinline__ float stencil1(
    float tL, float4 t4, float tR,
    float mL, float4 m4, float mR,
    float bL, float4 b4, float bR,
    int k)
{
    float t[6]  = {tL, t4.x, t4.y, t4.z, t4.w, tR};
    float m[6]  = {mL, m4.x, m4.y, m4.z, m4.w, mR};
    float bo[6] = {bL, b4.x, b4.y, b4.z, b4.w, bR};
    float g   = m[k + 1];
    float acc = 128.0f * t[k]  + 64.0f * t[k + 1] + 32.0f * t[k + 2]
              +   1.0f * m[k]  + 16.0f * m[k + 2]
              +   2.0f * bo[k] +  4.0f * bo[k + 1] + 8.0f * bo[k + 2];
    return 0.5f * (g + 1.0f) - (0.5f / 255.0f) * acc;
}

__global__ __launch_bounds__(256)
void ltpe_pass1(const float* __restrict__ x, float* __restrict__ out) {
    __shared__ float gs[SH * SSTRIDE];
    __shared__ float2 wred[8];

    const int b    = blockIdx.z;
    const int x0   = blockIdx.x * TW;
    const int y0   = blockIdx.y * TH;
    const int tx   = threadIdx.x;          // 0..63
    const int ty   = threadIdx.y;          // 0..3
    const int tid  = ty * 64 + tx;
    const int lane = tid & 31;
    const int cbase = 4 * tx;              // left edge scalar at smem col cbase+3

    const float* __restrict__ xr = x + (size_t)b * 3 * HW;
    const float* __restrict__ xg = xr + HW;
    const float* __restrict__ xb = xg + HW;

    // ---- Interior: 2 consecutive rows/thread, 6 float4 LDG in flight ----
    const int r0 = 2 * ty;                 // tile rows r0, r0+1 (smem rows r0+1, r0+2)
    float4 q0, q1;
    {
        const int gx = x0 + 4 * tx;
        const int o0 = (y0 + r0) * W + gx;
        const int o1 = o0 + W;
        float4 ra = __ldcs((const float4*)(xr + o0));
        float4 ga = __ldcs((const float4*)(xg + o0));
        float4 ba = __ldcs((const float4*)(xb + o0));
        float4 rb = __ldcs((const float4*)(xr + o1));
        float4 gb = __ldcs((const float4*)(xg + o1));
        float4 bb = __ldcs((const float4*)(xb + o1));
        q0 = make_float4(gray3(ra.x, ga.x, ba.x), gray3(ra.y, ga.y, ba.y),
                         gray3(ra.z, ga.z, ba.z), gray3(ra.w, ga.w, ba.w));
        q1 = make_float4(gray3(rb.x, gb.x, bb.x), gray3(rb.y, gb.y, bb.y),
                         gray3(rb.z, gb.z, bb.z), gray3(rb.w, gb.w, bb.w));
        *(float4*)(gs + (r0 + 1) * SSTRIDE + 4 + cbase) = q0;
        *(float4*)(gs + (r0 + 2) * SSTRIDE + 4 + cbase) = q1;
    }

    // ---- Row halos (smem rows 0 and 9): coalesced float4, tids 0..127 ----
    if (tid < 128) {
        const int top  = (tid < 64);
        const int lt   = top ? tid : (tid - 64);
        const int gy   = top ? (y0 - 1) : (y0 + TH);
        const int srow = top ? 0 : (SH - 1);
        float4 q = make_float4(0.f, 0.f, 0.f, 0.f);
        if (gy >= 0 && gy < H) {
            const int o = gy * W + x0 + 4 * lt;
            float4 r4 = __ldcs((const float4*)(xr + o));
            float4 g4 = __ldcs((const float4*)(xg + o));
            float4 b4 = __ldcs((const float4*)(xb + o));
            q = make_float4(gray3(r4.x, g4.x, b4.x), gray3(r4.y, g4.y, b4.y),
                            gray3(r4.z, g4.z, b4.z), gray3(r4.w, g4.w, b4.w));
        }
        *(float4*)(gs + srow * SSTRIDE + 4 + 4 * lt) = q;
    }
    // ---- Column halos (cols 3 and 260, all 10 rows): tids 128..147 ----
    else if (tid < 128 + 2 * SH) {
        const int j   = tid - 128;          // 0..19
        const int sr  = j >> 1;             // 0..9
        const int rgt = j & 1;
        const int gy  = y0 + sr - 1;
        const int gx  = rgt ? (x0 + TW) : (x0 - 1);
        float v = 0.0f;
        if (gy >= 0 && gy < H && gx >= 0 && gx < W) {
            const int o = gy * W + gx;
            v = gray3(__ldcs(xr + o), __ldcs(xg + o), __ldcs(xb + o));
        }
        gs[sr * SSTRIDE + (rgt ? 260 : 3)] = v;
    }
    __syncthreads();

    // ---- Fetch only the two vertical-neighbor rows from smem ----
    float4 t4 = *(const float4*)(gs + (r0    ) * SSTRIDE + 4 + cbase);  // row above pair
    float4 b4 = *(const float4*)(gs + (r0 + 3) * SSTRIDE + 4 + cbase);  // row below pair

    // ---- Edge scalars via register shuffles; warp-boundary lanes fall back to smem ----
    const unsigned FULL = 0xFFFFFFFFu;
    float tLs  = __shfl_up_sync  (FULL, t4.w, 1);
    float tRs  = __shfl_down_sync(FULL, t4.x, 1);
    float m0Ls = __shfl_up_sync  (FULL, q0.w, 1);
    float m0Rs = __shfl_down_sync(FULL, q0.x, 1);
    float m1Ls = __shfl_up_sync  (FULL, q1.w, 1);
    float m1Rs = __shfl_down_sync(FULL, q1.x, 1);
    float bLs  = __shfl_up_sync  (FULL, b4.w, 1);
    float bRs  = __shfl_down_sync(FULL, b4.x, 1);

    const bool l0  = (lane == 0);
    const bool l31 = (lane == 31);
    float tL  = l0  ? gs[(r0    ) * SSTRIDE + cbase + 3] : tLs;
    float m0L = l0  ? gs[(r0 + 1) * SSTRIDE + cbase + 3] : m0Ls;
    float m1L = l0  ? gs[(r0 + 2) * SSTRIDE + cbase + 3] : m1Ls;
    float bL  = l0  ? gs[(r0 + 3) * SSTRIDE + cbase + 3] : bLs;
    float tR  = l31 ? gs[(r0    ) * SSTRIDE + cbase + 8] : tRs;
    float m0R = l31 ? gs[(r0 + 1) * SSTRIDE + cbase + 8] : m0Rs;
    float m1R = l31 ? gs[(r0 + 2) * SSTRIDE + cbase + 8] : m1Rs;
    float bR  = l31 ? gs[(r0 + 3) * SSTRIDE + cbase + 8] : bRs;

    // ---- Stencil rows 2ty and 2ty+1 (middle rows come from registers) ----
    float s = 0.0f, s2 = 0.0f;
    float* __restrict__ obase = out + (size_t)b * 3 * HW;

    float4 ov0, ov1;
    float* op0 = (float*)&ov0;
    float* op1 = (float*)&ov1;
    #pragma unroll
    for (int k = 0; k < 4; k++) {
        float o0 = stencil1(tL,  t4, tR,   m0L, q0, m0R,  m1L, q1, m1R, k);
        float o1 = stencil1(m0L, q0, m0R,  m1L, q1, m1R,  bL,  b4, bR,  k);
        op0[k] = o0; op1[k] = o1;
        s  += o0 + o1;
        s2 += o0 * o0 + o1 * o1;
    }
    // scratch writes: default policy -> stays in L2 for pass 2
    *(float4*)(obase + (y0 + r0    ) * W + x0 + cbase) = ov0;
    *(float4*)(obase + (y0 + r0 + 1) * W + x0 + cbase) = ov1;

    // ---- Block reduction -> one float2 partial per block ----
    #pragma unroll
    for (int off = 16; off > 0; off >>= 1) {
        s  += __shfl_down_sync(FULL, s,  off);
        s2 += __shfl_down_sync(FULL, s2, off);
    }
    if (lane == 0) wred[tid >> 5] = make_float2(s, s2);
    __syncthreads();
    if (tid == 0) {
        float ts = 0.0f, ts2 = 0.0f;
        #pragma unroll
        for (int w = 0; w < 8; w++) { ts += wred[w].x; ts2 += wred[w].y; }
        g_part[b * PBLK + blockIdx.y * BLKX + blockIdx.x] = make_float2(ts, ts2);
    }
}

// Tiny per-batch reduction: 8 blocks x 256 threads over 512 partials each.
__global__ __launch_bounds__(256)
void ltpe_norm(void) {
    __shared__ double rs[8], rs2[8];
    const int b   = blockIdx.x;
    const int tid = threadIdx.x;

    float2 p0 = g_part[b * PBLK + tid];
    float2 p1 = g_part[b * PBLK + tid + 256];
    double s  = (double)p0.x + (double)p1.x;
    double s2 = (double)p0.y + (double)p1.y;
    #pragma unroll
    for (int off = 16; off > 0; off >>= 1) {
        s  += __shfl_down_sync(0xFFFFFFFFu, s,  off);
        s2 += __shfl_down_sync(0xFFFFFFFFu, s2, off);
    }
    if ((tid & 31) == 0) { rs[tid >> 5] = s; rs2[tid >> 5] = s2; }
    __syncthreads();
    if (tid == 0) {
        double ts = 0.0, ts2 = 0.0;
        #pragma unroll
        for (int w = 0; w < 8; w++) { ts += rs[w]; ts2 += rs2[w]; }
        double mean = ts * (1.0 / HW);
        double var  = ts2 * (1.0 / HW) - mean * mean;
        g_norm[b] = make_float2((float)mean, rsqrtf((float)var + 1e-5f));
    }
}

// Pass 2: each thread handles 4 independent float4 chunks (MLP=4).
__global__ __launch_bounds__(256)
void ltpe_pass2(float* __restrict__ out) {
    const int b   = blockIdx.y;
    const int tid = threadIdx.x;

    const float2 nm  = g_norm[b];
    const float m    = nm.x;
    const float rstd = nm.y;

    float* __restrict__ base = out + (size_t)b * 3 * HW;
    const int i0 = blockIdx.x * (256 * 4 * 4);   // floats

    float4 v[4];
    #pragma unroll
    for (int k = 0; k < 4; k++)
        v[k] = __ldcs((const float4*)(base + i0 + (k * 256 + tid) * 4));

    #pragma unroll
    for (int k = 0; k < 4; k++) {
        v[k].x = (v[k].x - m) * rstd;
        v[k].y = (v[k].y - m) * rstd;
        v[k].z = (v[k].z - m) * rstd;
        v[k].w = (v[k].w - m) * rstd;
    }

    #pragma unroll
    for (int k = 0; k < 4; k++) {
        const int i = i0 + (k * 256 + tid) * 4;
        __stcs((float4*)(base + i),          v[k]);
        __stcs((float4*)(base + HW + i),     v[k]);
        __stcs((float4*)(base + 2 * HW + i), v[k]);
    }
}

extern "C" void kernel_launch(void* const* d_in, const int* in_sizes, int n_in,
                              void* d_out, int out_size) {
    const float* x = (const float*)d_in[0];
    float* out = (float*)d_out;

    dim3 blk1(64, 4);
    dim3 grd1(BLKX, BLKY, BATCH);
    ltpe_pass1<<<grd1, blk1>>>(x, out);

    ltpe_norm<<<BATCH, 256>>>();

    dim3 grd2(HW / 4 / 256 / 4, BATCH);   // 256 x 8
    ltpe_pass2<<<grd2, 256>>>(out);
}